// round 5
// baseline (speedup 1.0000x reference)
#include <cuda_runtime.h>

// LIF layer scan: B=64, F=256, L=2048.  out = [z | s], each B*F*L float32.
//
// 2 CTAs/SM (grid=256, 192 threads):
//   tid  0..63  : scan warps — one row each, serial over time
//   tid 64..191 : mem warps  — pure float4 LDG/STS and LDS/STG copies
// All SMEM traffic is 128-bit, conflict-free via float4-slot swizzle:
//   tile[64 rows][16 float4], slot(r, tb) = r*16 + (tb ^ (r & 7))
// s is reconstructed as (z >= 0): exact since z = fma(15, v_pre, -3.75) and
// 15*0.25 is exactly representable.

#define BB 64
#define FF 256
#define LL 2048
#define ROWS 64
#define CHUNK 64
#define NTHREADS 192
#define NMEM 128
#define TILE4 (ROWS * 16)       // float4 slots per tile = 1024

#define BETA 15.0f
#define DT 1.0f

__device__ __forceinline__ int slot(int r, int tb) {
    return r * 16 + (tb ^ (r & 7));
}

__global__ __launch_bounds__(NTHREADS, 2)
void lif_kernel(const float* __restrict__ I,
                const float* __restrict__ raw_tau,
                const float* __restrict__ thr_p,
                float* __restrict__ out)
{
    extern __shared__ float4 smem4[];
    float4* inb = smem4;                 // 2 * TILE4
    float4* zb  = inb + 2 * TILE4;       // 2 * TILE4

    const int tid = threadIdx.x;
    const long long row0 = (long long)blockIdx.x * ROWS;
    const float thr = thr_p[0];

    float v = 0.0f, alpha = 0.0f, one_m_alpha = 0.0f;
    if (tid < ROWS) {
        int f = (int)((row0 + tid) % FF);
        float rt = raw_tau[f];
        float sp = fmaxf(rt, 0.0f) + log1pf(expf(-fabsf(rt)));  // stable softplus
        float tau = sp + 1e-4f;
        alpha = expf(-DT / tau);
        one_m_alpha = 1.0f - alpha;
    }
    const float beta_thr = BETA * thr;

    const float* Iblk = I + row0 * LL;
    float* zg = out;
    float* sg = out + (long long)BB * FF * LL;
    const int nchunks = LL / CHUNK;

    // ---- preload chunk 0: 1024 float4, 128 mem threads x 8, direct copy ----
    if (tid >= ROWS) {
        const int m = tid - ROWS;
        #pragma unroll
        for (int i = 0; i < 8; i++) {
            int idx = m + i * NMEM;            // 0..1023
            int r = idx >> 4, c4 = idx & 15;
            float4 v4 = __ldcs((const float4*)(Iblk + (long long)r * LL + c4 * 4));
            inb[slot(r, c4)] = v4;
        }
    }
    __syncthreads();

    for (int k = 0; k < nchunks; k++) {
        if (tid < ROWS) {
            // ---- scan warps: chunk k, 4 steps per float4 ----
            const float4* ip = inb + (k & 1) * TILE4;
            float4* zp = zb + (k & 1) * TILE4;
            const int base = tid * 16;
            const int sw = tid & 7;
            float vv = v;
            #pragma unroll
            for (int tb = 0; tb < 16; tb++) {
                const int sl = base + (tb ^ sw);
                float4 in4 = ip[sl];             // LDS.128, off-chain
                float4 z4;
                float v_pre;
                v_pre = fmaf(alpha, vv, one_m_alpha * in4.x);
                z4.x = fmaf(BETA, v_pre, -beta_thr);
                vv = (v_pre >= thr) ? 0.0f : v_pre;
                v_pre = fmaf(alpha, vv, one_m_alpha * in4.y);
                z4.y = fmaf(BETA, v_pre, -beta_thr);
                vv = (v_pre >= thr) ? 0.0f : v_pre;
                v_pre = fmaf(alpha, vv, one_m_alpha * in4.z);
                z4.z = fmaf(BETA, v_pre, -beta_thr);
                vv = (v_pre >= thr) ? 0.0f : v_pre;
                v_pre = fmaf(alpha, vv, one_m_alpha * in4.w);
                z4.w = fmaf(BETA, v_pre, -beta_thr);
                vv = (v_pre >= thr) ? 0.0f : v_pre;
                zp[sl] = z4;                     // STS.128
            }
            v = vv;
        } else {
            const int m = tid - ROWS;
            // ---- mem warps: load chunk k+1 (direct float4 copy) ----
            if (k + 1 < nchunks) {
                const int t0n = (k + 1) * CHUNK;
                float4* d = inb + ((k + 1) & 1) * TILE4;
                #pragma unroll
                for (int i = 0; i < 8; i++) {
                    int idx = m + i * NMEM;
                    int r = idx >> 4, c4 = idx & 15;
                    float4 v4 = __ldcs((const float4*)(Iblk + (long long)r * LL + t0n + c4 * 4));
                    d[slot(r, c4)] = v4;
                }
            }
            // ---- mem warps: store chunk k-1 (z + reconstructed s) ----
            if (k >= 1) {
                const int km = k - 1;
                const int t0m = km * CHUNK;
                const float4* zp = zb + (km & 1) * TILE4;
                #pragma unroll
                for (int i = 0; i < 8; i++) {
                    int idx = m + i * NMEM;
                    int r = idx >> 4, c4 = idx & 15;
                    float4 z4 = zp[slot(r, c4)];      // LDS.128
                    float4 s4;
                    s4.x = (z4.x >= 0.0f) ? 1.0f : 0.0f;
                    s4.y = (z4.y >= 0.0f) ? 1.0f : 0.0f;
                    s4.z = (z4.z >= 0.0f) ? 1.0f : 0.0f;
                    s4.w = (z4.w >= 0.0f) ? 1.0f : 0.0f;
                    long long go = (row0 + r) * (long long)LL + t0m + c4 * 4;
                    __stcs((float4*)(zg + go), z4);
                    __stcs((float4*)(sg + go), s4);
                }
            }
        }
        __syncthreads();
    }

    // ---- tail: store last chunk ----
    if (tid >= ROWS) {
        const int m = tid - ROWS;
        const int km = nchunks - 1;
        const int t0m = km * CHUNK;
        const float4* zp = zb + (km & 1) * TILE4;
        #pragma unroll
        for (int i = 0; i < 8; i++) {
            int idx = m + i * NMEM;
            int r = idx >> 4, c4 = idx & 15;
            float4 z4 = zp[slot(r, c4)];
            float4 s4;
            s4.x = (z4.x >= 0.0f) ? 1.0f : 0.0f;
            s4.y = (z4.y >= 0.0f) ? 1.0f : 0.0f;
            s4.z = (z4.z >= 0.0f) ? 1.0f : 0.0f;
            s4.w = (z4.w >= 0.0f) ? 1.0f : 0.0f;
            long long go = (row0 + r) * (long long)LL + t0m + c4 * 4;
            __stcs((float4*)(zg + go), z4);
            __stcs((float4*)(sg + go), s4);
        }
    }
}

extern "C" void kernel_launch(void* const* d_in, const int* in_sizes, int n_in,
                              void* d_out, int out_size)
{
    const float* I       = (const float*)d_in[0];
    const float* raw_tau = (const float*)d_in[1];
    const float* thr     = (const float*)d_in[2];
    float* out           = (float*)d_out;

    const int smem_bytes = 4 * TILE4 * (int)sizeof(float4);  // 65536
    cudaFuncSetAttribute(lif_kernel, cudaFuncAttributeMaxDynamicSharedMemorySize,
                         smem_bytes);

    const int nblocks = (BB * FF) / ROWS;  // 256
    lif_kernel<<<nblocks, NTHREADS, smem_bytes>>>(I, raw_tau, thr, out);
}

// round 6
// speedup vs baseline: 1.0299x; 1.0299x over previous
#include <cuda_runtime.h>
#include <cstdint>

// LIF layer scan: B=64, F=256, L=2048.  out = [z | s], each B*F*L float32.
//
// mbarrier producer/consumer rings (no block-wide barriers in the main loop):
//   tid  0..63  : scan warps — one row each, serial over time
//   tid 64..191 : mem warps  — float4 LDG/STS (input) + LDS/STG (z,s)
// Input ring: 4 stages (mem -> scan). z ring: 2 stages (scan -> mem).
// s reconstructed as (z >= 0): exact since z = fma(15, v_pre, -3.75), 15*0.25 exact.
// SMEM tiles [64 rows][16 float4], slot(r,tb) = r*16 + (tb ^ (r&7)): conflict-free
// for both access patterns. 2 CTAs/SM (grid=256).

#define BB 64
#define FF 256
#define LL 2048
#define ROWS 64
#define CHUNK 64
#define NTHREADS 192
#define NMEM 128
#define TILE4 (ROWS * 16)     // 1024 float4 per tile
#define IN_ST 4
#define Z_ST 2

#define BETA 15.0f
#define DT 1.0f

// barrier byte offsets within smem (data starts at 128)
#define BAR_IN_FULL(s)  ((s) * 8)
#define BAR_IN_EMPTY(s) (32 + (s) * 8)
#define BAR_Z_FULL(s)   (64 + (s) * 8)
#define BAR_Z_EMPTY(s)  (80 + (s) * 8)
#define DATA_OFF 128

__device__ __forceinline__ int slot(int r, int tb) {
    return r * 16 + (tb ^ (r & 7));
}

__device__ __forceinline__ void mbar_init(uint32_t addr, uint32_t count) {
    asm volatile("mbarrier.init.shared.b64 [%0], %1;" :: "r"(addr), "r"(count) : "memory");
}
__device__ __forceinline__ void mbar_arrive(uint32_t addr) {
    asm volatile("mbarrier.arrive.shared.b64 _, [%0];" :: "r"(addr) : "memory");
}
__device__ __forceinline__ void mbar_wait(uint32_t addr, uint32_t parity) {
    asm volatile(
        "{\n\t.reg .pred P;\n\t"
        "WL_%=:\n\t"
        "mbarrier.try_wait.parity.acquire.cta.shared::cta.b64 P, [%0], %1, 0x989680;\n\t"
        "@P bra.uni WD_%=;\n\t"
        "bra.uni WL_%=;\n\t"
        "WD_%=:\n\t}"
        :: "r"(addr), "r"(parity) : "memory");
}

__global__ __launch_bounds__(NTHREADS, 2)
void lif_kernel(const float* __restrict__ I,
                const float* __restrict__ raw_tau,
                const float* __restrict__ thr_p,
                float* __restrict__ out)
{
    extern __shared__ char smem[];
    uint32_t sbase;
    asm("{ .reg .u64 t; cvta.to.shared.u64 t, %1; cvt.u32.u64 %0, t; }"
        : "=r"(sbase) : "l"(smem));
    float4* inb = (float4*)(smem + DATA_OFF);          // IN_ST * TILE4
    float4* zb  = inb + IN_ST * TILE4;                 // Z_ST * TILE4

    const int tid = threadIdx.x;
    const long long row0 = (long long)blockIdx.x * ROWS;
    const float thr = thr_p[0];
    const int nchunks = LL / CHUNK;                    // 32

    if (tid == 0) {
        #pragma unroll
        for (int s = 0; s < IN_ST; s++) {
            mbar_init(sbase + BAR_IN_FULL(s), NMEM);   // 128 mem-thread arrivals
            mbar_init(sbase + BAR_IN_EMPTY(s), ROWS);  // 64 scan-thread arrivals
        }
        #pragma unroll
        for (int s = 0; s < Z_ST; s++) {
            mbar_init(sbase + BAR_Z_FULL(s), ROWS);
            mbar_init(sbase + BAR_Z_EMPTY(s), NMEM);
        }
    }
    __syncthreads();   // barriers visible before any arrive/wait

    const float* Iblk = I + row0 * LL;
    float* zg = out;
    float* sg = out + (long long)BB * FF * LL;

    if (tid < ROWS) {
        // ================= scan warps =================
        int f = (int)((row0 + tid) % FF);
        float rt = raw_tau[f];
        float sp = fmaxf(rt, 0.0f) + log1pf(expf(-fabsf(rt)));  // stable softplus
        float tau = sp + 1e-4f;
        float alpha = expf(-DT / tau);
        float one_m_alpha = 1.0f - alpha;
        const float beta_thr = BETA * thr;

        const int base = tid * 16;
        const int sw = tid & 7;
        float vv = 0.0f;

        for (int k = 0; k < nchunks; k++) {
            const int si = k & (IN_ST - 1);
            const int zs = k & (Z_ST - 1);
            mbar_wait(sbase + BAR_IN_FULL(si), (k >> 2) & 1);          // consumer
            mbar_wait(sbase + BAR_Z_EMPTY(zs), (((k >> 1) & 1) ^ 1));  // producer
            const float4* ip = inb + si * TILE4;
            float4* zp = zb + zs * TILE4;
            #pragma unroll
            for (int tb = 0; tb < 16; tb++) {
                const int sl = base + (tb ^ sw);
                float4 in4 = ip[sl];                 // LDS.128
                float4 z4;
                float v_pre;
                v_pre = fmaf(alpha, vv, one_m_alpha * in4.x);
                z4.x = fmaf(BETA, v_pre, -beta_thr);
                vv = (v_pre >= thr) ? 0.0f : v_pre;
                v_pre = fmaf(alpha, vv, one_m_alpha * in4.y);
                z4.y = fmaf(BETA, v_pre, -beta_thr);
                vv = (v_pre >= thr) ? 0.0f : v_pre;
                v_pre = fmaf(alpha, vv, one_m_alpha * in4.z);
                z4.z = fmaf(BETA, v_pre, -beta_thr);
                vv = (v_pre >= thr) ? 0.0f : v_pre;
                v_pre = fmaf(alpha, vv, one_m_alpha * in4.w);
                z4.w = fmaf(BETA, v_pre, -beta_thr);
                vv = (v_pre >= thr) ? 0.0f : v_pre;
                zp[sl] = z4;                         // STS.128
            }
            mbar_arrive(sbase + BAR_IN_EMPTY(si));
            mbar_arrive(sbase + BAR_Z_FULL(zs));
        }
    } else {
        // ================= mem warps =================
        const int m = tid - ROWS;
        for (int j = 0; j <= nchunks; j++) {
            float4 regs[8];
            // 1) issue global loads for chunk j (no wait needed: registers)
            if (j < nchunks) {
                const int t0 = j * CHUNK;
                #pragma unroll
                for (int i = 0; i < 8; i++) {
                    int idx = m + i * NMEM;
                    int r = idx >> 4, c4 = idx & 15;
                    regs[i] = __ldcs((const float4*)(Iblk + (long long)r * LL + t0 + c4 * 4));
                }
            }
            // 2) store chunk j-1 (z + reconstructed s)
            if (j >= 1) {
                const int km = j - 1;
                const int zs = km & (Z_ST - 1);
                mbar_wait(sbase + BAR_Z_FULL(zs), (km >> 1) & 1);      // consumer
                const float4* zp = zb + zs * TILE4;
                const int t0m = km * CHUNK;
                #pragma unroll
                for (int i = 0; i < 8; i++) {
                    int idx = m + i * NMEM;
                    int r = idx >> 4, c4 = idx & 15;
                    float4 z4 = zp[slot(r, c4)];     // LDS.128
                    float4 s4;
                    s4.x = (z4.x >= 0.0f) ? 1.0f : 0.0f;
                    s4.y = (z4.y >= 0.0f) ? 1.0f : 0.0f;
                    s4.z = (z4.z >= 0.0f) ? 1.0f : 0.0f;
                    s4.w = (z4.w >= 0.0f) ? 1.0f : 0.0f;
                    long long go = (row0 + r) * (long long)LL + t0m + c4 * 4;
                    __stcs((float4*)(zg + go), z4);
                    __stcs((float4*)(sg + go), s4);
                }
                mbar_arrive(sbase + BAR_Z_EMPTY(zs));
            }
            // 3) commit chunk j input to SMEM ring
            if (j < nchunks) {
                const int si = j & (IN_ST - 1);
                mbar_wait(sbase + BAR_IN_EMPTY(si), (((j >> 2) & 1) ^ 1));  // producer
                float4* d = inb + si * TILE4;
                #pragma unroll
                for (int i = 0; i < 8; i++) {
                    int idx = m + i * NMEM;
                    int r = idx >> 4, c4 = idx & 15;
                    d[slot(r, c4)] = regs[i];        // STS.128
                }
                mbar_arrive(sbase + BAR_IN_FULL(si));
            }
        }
    }
}

extern "C" void kernel_launch(void* const* d_in, const int* in_sizes, int n_in,
                              void* d_out, int out_size)
{
    const float* I       = (const float*)d_in[0];
    const float* raw_tau = (const float*)d_in[1];
    const float* thr     = (const float*)d_in[2];
    float* out           = (float*)d_out;

    const int smem_bytes = DATA_OFF + (IN_ST + Z_ST) * TILE4 * (int)sizeof(float4); // 98432
    cudaFuncSetAttribute(lif_kernel, cudaFuncAttributeMaxDynamicSharedMemorySize,
                         smem_bytes);

    const int nblocks = (BB * FF) / ROWS;  // 256
    lif_kernel<<<nblocks, NTHREADS, smem_bytes>>>(I, raw_tau, thr, out);
}

// round 7
// speedup vs baseline: 1.0865x; 1.0550x over previous
#include <cuda_runtime.h>
#include <cuda.h>
#include <cstdint>

// LIF layer scan: B=64, F=256, L=2048.  out = [z | s], each B*F*L float32.
//
// Full-TMA dataflow: SMs never issue per-lane global loads/stores.
//   - Input I staged by UTMALDG (2D TMA, SW128, box [32 floats x 64 rows]),
//     2-deep ring, tx-mbarrier completion.
//   - z and s written by scan threads into SW128-layout SMEM tiles, then
//     bulk-stored by UTMASTG (4 tiles/chunk), 2-deep ring, bulk_group pacing.
//   - Block = 64 threads (one per row), grid = 256, 2 CTAs/SM.
// s = spike indicator computed inline from the scan predicate (exact).
// SW128 swizzle inside a [64 r][128 B] tile: 16B-quad q at physical q ^ (r&7)
// -> conflict-free LDS/STS per quarter-warp for thread==row access.

#define BB 64
#define FF 256
#define LL 2048
#define ROWS 64
#define CHUNK 64
#define NTH 64
#define NCH (LL / CHUNK)     // 32

#define BETA 15.0f
#define DT 1.0f

// smem byte offsets
#define BAR(s)   ((s) * 8)                  // FULL_IN mbarriers, stages 0,1
#define IN_OFF   1024                        // 2 stages x 16384 (2 halves x 8192)
#define ST_OFF   (1024 + 32768)              // 2 slots x 32768: [z0 z1 s0 s1] x 8192
#define SMEM_BYTES (1024 + 32768 + 65536)    // 99328

__device__ __forceinline__ void mbar_init(uint32_t a, uint32_t c) {
    asm volatile("mbarrier.init.shared.b64 [%0], %1;" :: "r"(a), "r"(c) : "memory");
}
__device__ __forceinline__ void mbar_expect_tx(uint32_t a, uint32_t bytes) {
    asm volatile("mbarrier.arrive.expect_tx.shared.b64 _, [%0], %1;"
                 :: "r"(a), "r"(bytes) : "memory");
}
__device__ __forceinline__ void mbar_wait(uint32_t a, uint32_t parity) {
    asm volatile(
        "{\n\t.reg .pred P;\n\t"
        "WL_%=:\n\t"
        "mbarrier.try_wait.parity.acquire.cta.shared::cta.b64 P, [%0], %1, 0x989680;\n\t"
        "@P bra.uni WD_%=;\n\t"
        "bra.uni WL_%=;\n\t"
        "WD_%=:\n\t}"
        :: "r"(a), "r"(parity) : "memory");
}
__device__ __forceinline__ void tma_load_2d(uint32_t smem, const CUtensorMap* m,
                                            int x, int y, uint32_t bar) {
    asm volatile(
        "cp.async.bulk.tensor.2d.shared::cta.global.tile.mbarrier::complete_tx::bytes "
        "[%0], [%1, {%2, %3}], [%4];"
        :: "r"(smem), "l"(m), "r"(x), "r"(y), "r"(bar) : "memory");
}
__device__ __forceinline__ void tma_store_2d(const CUtensorMap* m,
                                             int x, int y, uint32_t smem) {
    asm volatile(
        "cp.async.bulk.tensor.2d.global.shared::cta.tile.bulk_group "
        "[%0, {%1, %2}], [%3];"
        :: "l"(m), "r"(x), "r"(y), "r"(smem) : "memory");
}

__global__ __launch_bounds__(NTH, 2)
void lif_tma_kernel(const __grid_constant__ CUtensorMap tin,
                    const __grid_constant__ CUtensorMap tz,
                    const __grid_constant__ CUtensorMap tsm,
                    const float* __restrict__ raw_tau,
                    const float* __restrict__ thr_p)
{
    extern __shared__ char smem[];
    uint32_t sb;
    asm("{ .reg .u64 t; cvta.to.shared.u64 t, %1; cvt.u32.u64 %0, t; }"
        : "=r"(sb) : "l"(smem));

    const int tid = threadIdx.x;              // = row within block
    const int row0 = blockIdx.x * ROWS;

    // per-row constants
    const float thr = thr_p[0];
    float rt = raw_tau[(row0 + tid) % FF];
    float sp = fmaxf(rt, 0.0f) + log1pf(expf(-fabsf(rt)));   // stable softplus
    float tau = sp + 1e-4f;
    const float alpha = expf(-DT / tau);
    const float one_m_alpha = 1.0f - alpha;
    const float beta_thr = BETA * thr;

    if (tid == 0) {
        mbar_init(sb + BAR(0), 1);
        mbar_init(sb + BAR(1), 1);
    }
    __syncthreads();

    // prologue: load stages 0,1
    if (tid == 0) {
        #pragma unroll
        for (int s = 0; s < 2; s++) {
            mbar_expect_tx(sb + BAR(s), 16384);
            tma_load_2d(sb + IN_OFF + s * 16384,        &tin, s * CHUNK,      row0, sb + BAR(s));
            tma_load_2d(sb + IN_OFF + s * 16384 + 8192, &tin, s * CHUNK + 32, row0, sb + BAR(s));
        }
    }

    const int sw = tid & 7;
    const uint32_t rbase = (uint32_t)tid * 128;  // row offset within 8KB tile
    float vv = 0.0f;

    for (int k = 0; k < NCH; k++) {
        const int si = k & 1;
        mbar_wait(sb + BAR(si), (k >> 1) & 1);

        const char* ib = smem + IN_OFF + si * 16384 + rbase;
        char* zt = smem + ST_OFF + si * 32768 + rbase;           // z tiles
        char* st = zt + 16384;                                   // s tiles

        #pragma unroll
        for (int tb = 0; tb < 16; tb++) {
            const uint32_t off = ((tb >> 3) * 8192) + ((uint32_t)((tb & 7) ^ sw) << 4);
            float4 in4 = *(const float4*)(ib + off);             // LDS.128
            float4 z4, s4;
            float v_pre; bool spk;
            v_pre = fmaf(alpha, vv, one_m_alpha * in4.x);
            z4.x = fmaf(BETA, v_pre, -beta_thr);
            spk = (v_pre >= thr); s4.x = spk ? 1.0f : 0.0f; vv = spk ? 0.0f : v_pre;
            v_pre = fmaf(alpha, vv, one_m_alpha * in4.y);
            z4.y = fmaf(BETA, v_pre, -beta_thr);
            spk = (v_pre >= thr); s4.y = spk ? 1.0f : 0.0f; vv = spk ? 0.0f : v_pre;
            v_pre = fmaf(alpha, vv, one_m_alpha * in4.z);
            z4.z = fmaf(BETA, v_pre, -beta_thr);
            spk = (v_pre >= thr); s4.z = spk ? 1.0f : 0.0f; vv = spk ? 0.0f : v_pre;
            v_pre = fmaf(alpha, vv, one_m_alpha * in4.w);
            z4.w = fmaf(BETA, v_pre, -beta_thr);
            spk = (v_pre >= thr); s4.w = spk ? 1.0f : 0.0f; vv = spk ? 0.0f : v_pre;
            *(float4*)(zt + off) = z4;                           // STS.128
            *(float4*)(st + off) = s4;                           // STS.128
        }
        __syncthreads();   // tiles complete; input slot fully consumed

        if (tid == 0) {
            asm volatile("fence.proxy.async.shared::cta;" ::: "memory");
            const int t0 = k * CHUNK;
            const uint32_t slot = sb + ST_OFF + si * 32768;
            tma_store_2d(&tz,  t0,      row0, slot);
            tma_store_2d(&tz,  t0 + 32, row0, slot + 8192);
            tma_store_2d(&tsm, t0,      row0, slot + 16384);
            tma_store_2d(&tsm, t0 + 32, row0, slot + 24576);
            asm volatile("cp.async.bulk.commit_group;" ::: "memory");
            if (k + 2 < NCH) {
                const int tn = (k + 2) * CHUNK;
                mbar_expect_tx(sb + BAR(si), 16384);
                tma_load_2d(sb + IN_OFF + si * 16384,        &tin, tn,      row0, sb + BAR(si));
                tma_load_2d(sb + IN_OFF + si * 16384 + 8192, &tin, tn + 32, row0, sb + BAR(si));
            }
            // ensure store group k-1 done before slot (k+1)&1 is rewritten
            asm volatile("cp.async.bulk.wait_group 1;" ::: "memory");
        }
        __syncthreads();
    }

    if (tid == 0)
        asm volatile("cp.async.bulk.wait_group 0;" ::: "memory");
}

// ---------------- host side ----------------

typedef CUresult (*EncodeFn)(CUtensorMap*, CUtensorMapDataType, cuuint32_t, void*,
                             const cuuint64_t*, const cuuint64_t*,
                             const cuuint32_t*, const cuuint32_t*,
                             CUtensorMapInterleave, CUtensorMapSwizzle,
                             CUtensorMapL2promotion, CUtensorMapFloatOOBfill);

static void make_map(EncodeFn enc, CUtensorMap* m, void* base) {
    cuuint64_t dims[2]    = {LL, (cuuint64_t)BB * FF};
    cuuint64_t strides[1] = {LL * sizeof(float)};
    cuuint32_t box[2]     = {32, ROWS};      // 128B x 64 rows, SW128
    cuuint32_t es[2]      = {1, 1};
    enc(m, CU_TENSOR_MAP_DATA_TYPE_FLOAT32, 2, base, dims, strides, box, es,
        CU_TENSOR_MAP_INTERLEAVE_NONE, CU_TENSOR_MAP_SWIZZLE_128B,
        CU_TENSOR_MAP_L2_PROMOTION_L2_128B, CU_TENSOR_MAP_FLOAT_OOB_FILL_NONE);
}

extern "C" void kernel_launch(void* const* d_in, const int* in_sizes, int n_in,
                              void* d_out, int out_size)
{
    float* I       = (float*)d_in[0];
    const float* raw_tau = (const float*)d_in[1];
    const float* thr     = (const float*)d_in[2];
    float* out           = (float*)d_out;

    static EncodeFn enc = nullptr;
    if (!enc) {
        cudaDriverEntryPointQueryResult qr;
        void* fp = nullptr;
        cudaGetDriverEntryPoint("cuTensorMapEncodeTiled", &fp,
                                cudaEnableDefault, &qr);
        enc = (EncodeFn)fp;
        cudaFuncSetAttribute(lif_tma_kernel,
                             cudaFuncAttributeMaxDynamicSharedMemorySize, SMEM_BYTES);
    }
    if (!enc) return;  // loud failure: bench will report mismatch

    CUtensorMap tin, tz, ts;
    make_map(enc, &tin, I);
    make_map(enc, &tz,  out);
    make_map(enc, &ts,  out + (size_t)BB * FF * LL);

    lif_tma_kernel<<<(BB * FF) / ROWS, NTH, SMEM_BYTES>>>(tin, tz, ts, raw_tau, thr);
}

// round 9
// speedup vs baseline: 1.1455x; 1.0543x over previous
#include <cuda_runtime.h>
#include <cuda.h>
#include <cstdint>

// LIF layer scan: B=64, F=256, L=2048.  out = [z | s], each B*F*L float32.
//
// Balanced persistent TMA kernel: grid=148 (one CTA per SM).
//   blocks 0..103 own 111 rows, blocks 104..147 own 110 rows (104*111+44*110=16384).
//   Two tensor-map variants per tensor (box height 111/110) -> exact TMA, no OOB.
// All SMEM tile bases are 1024-aligned (TILE_STRIDE=14336) so the SW128 hardware
// swizzle matches the in-kernel quad^(r&7) formula (fixes R8's corruption).
// Dataflow: UTMALDG input ring (2 stages, tx-mbarrier); scan threads
// (1 row/thread) LDS/STS through SW128 tiles; UTMASTG z+s (2 slots, bulk_group).

#define BB 64
#define FF 256
#define LL 2048
#define CHUNK 64
#define NTH 128
#define NCH (LL / CHUNK)     // 32
#define NBIG 104

#define BETA 15.0f
#define DT 1.0f

#define TILE_STRIDE 14336                 // 111*128=14208 padded to 14*1024
#define IN_STG  (2 * TILE_STRIDE)         // input stage: 2 half-tiles
#define ST_SLOT (4 * TILE_STRIDE)         // store slot: z0 z1 s0 s1
#define BARB(s) ((s) * 8)
#define IN_OFF  1024
#define ST_OFF  (IN_OFF + 2 * IN_STG)     // 1024 + 57344 = 58368 (1024-aligned)
#define SMEM_BYTES (ST_OFF + 2 * ST_SLOT) // 173056

__device__ __forceinline__ void mbar_init(uint32_t a, uint32_t c) {
    asm volatile("mbarrier.init.shared.b64 [%0], %1;" :: "r"(a), "r"(c) : "memory");
}
__device__ __forceinline__ void mbar_expect_tx(uint32_t a, uint32_t bytes) {
    asm volatile("mbarrier.arrive.expect_tx.shared.b64 _, [%0], %1;"
                 :: "r"(a), "r"(bytes) : "memory");
}
__device__ __forceinline__ void mbar_wait(uint32_t a, uint32_t parity) {
    asm volatile(
        "{\n\t.reg .pred P;\n\t"
        "WL_%=:\n\t"
        "mbarrier.try_wait.parity.acquire.cta.shared::cta.b64 P, [%0], %1, 0x989680;\n\t"
        "@P bra.uni WD_%=;\n\t"
        "bra.uni WL_%=;\n\t"
        "WD_%=:\n\t}"
        :: "r"(a), "r"(parity) : "memory");
}
__device__ __forceinline__ void tma_load_2d(uint32_t smem, const CUtensorMap* m,
                                            int x, int y, uint32_t bar) {
    asm volatile(
        "cp.async.bulk.tensor.2d.shared::cta.global.tile.mbarrier::complete_tx::bytes "
        "[%0], [%1, {%2, %3}], [%4];"
        :: "r"(smem), "l"(m), "r"(x), "r"(y), "r"(bar) : "memory");
}
__device__ __forceinline__ void tma_store_2d(const CUtensorMap* m,
                                             int x, int y, uint32_t smem) {
    asm volatile(
        "cp.async.bulk.tensor.2d.global.shared::cta.tile.bulk_group "
        "[%0, {%1, %2}], [%3];"
        :: "l"(m), "r"(x), "r"(y), "r"(smem) : "memory");
}

__global__ __launch_bounds__(NTH, 1)
void lif_tma_kernel(const __grid_constant__ CUtensorMap tin_a,
                    const __grid_constant__ CUtensorMap tin_b,
                    const __grid_constant__ CUtensorMap tz_a,
                    const __grid_constant__ CUtensorMap tz_b,
                    const __grid_constant__ CUtensorMap ts_a,
                    const __grid_constant__ CUtensorMap ts_b,
                    const float* __restrict__ raw_tau,
                    const float* __restrict__ thr_p)
{
    extern __shared__ char smem[];
    uint32_t sb;
    asm("{ .reg .u64 t; cvta.to.shared.u64 t, %1; cvt.u32.u64 %0, t; }"
        : "=r"(sb) : "l"(smem));

    const int tid = threadIdx.x;
    const int bid = blockIdx.x;
    const bool big = (bid < NBIG);
    const int H = big ? 111 : 110;
    const int row0 = big ? bid * 111 : NBIG * 111 + (bid - NBIG) * 110;
    const CUtensorMap* tin = big ? &tin_a : &tin_b;
    const CUtensorMap* tz  = big ? &tz_a  : &tz_b;
    const CUtensorMap* tsm = big ? &ts_a  : &ts_b;
    const uint32_t tx_bytes = (uint32_t)H * 256;   // 2 half-tiles x H x 128B

    // per-row constants
    const float thr = thr_p[0];
    const bool active = (tid < H);
    float alpha = 0.0f, one_m_alpha = 0.0f;
    if (active) {
        float rt = raw_tau[(row0 + tid) % FF];
        float sp = fmaxf(rt, 0.0f) + log1pf(expf(-fabsf(rt)));  // stable softplus
        float tau = sp + 1e-4f;
        alpha = expf(-DT / tau);
        one_m_alpha = 1.0f - alpha;
    }
    const float beta_thr = BETA * thr;

    if (tid == 0) {
        mbar_init(sb + BARB(0), 1);
        mbar_init(sb + BARB(1), 1);
    }
    __syncthreads();

    // prologue: input stages 0 and 1
    if (tid == 0) {
        #pragma unroll
        for (int s = 0; s < 2; s++) {
            mbar_expect_tx(sb + BARB(s), tx_bytes);
            const uint32_t dst = sb + IN_OFF + s * IN_STG;
            tma_load_2d(dst,               tin, s * CHUNK,      row0, sb + BARB(s));
            tma_load_2d(dst + TILE_STRIDE, tin, s * CHUNK + 32, row0, sb + BARB(s));
        }
    }

    const int sw = tid & 7;
    const uint32_t rbase = (uint32_t)tid * 128;
    float vv = 0.0f;

    for (int k = 0; k < NCH; k++) {
        const int si = k & 1;
        mbar_wait(sb + BARB(si), (k >> 1) & 1);

        if (active) {
            const char* ib = smem + IN_OFF + si * IN_STG + rbase;
            char* zt = smem + ST_OFF + si * ST_SLOT + rbase;
            char* st = zt + 2 * TILE_STRIDE;
            #pragma unroll
            for (int tb = 0; tb < 16; tb++) {
                const uint32_t off = (uint32_t)(tb >> 3) * TILE_STRIDE
                                   + ((uint32_t)((tb & 7) ^ sw) << 4);
                float4 in4 = *(const float4*)(ib + off);          // LDS.128
                float4 z4, s4;
                float v_pre; bool spk;
                v_pre = fmaf(alpha, vv, one_m_alpha * in4.x);
                z4.x = fmaf(BETA, v_pre, -beta_thr);
                spk = (v_pre >= thr); s4.x = spk ? 1.0f : 0.0f; vv = spk ? 0.0f : v_pre;
                v_pre = fmaf(alpha, vv, one_m_alpha * in4.y);
                z4.y = fmaf(BETA, v_pre, -beta_thr);
                spk = (v_pre >= thr); s4.y = spk ? 1.0f : 0.0f; vv = spk ? 0.0f : v_pre;
                v_pre = fmaf(alpha, vv, one_m_alpha * in4.z);
                z4.z = fmaf(BETA, v_pre, -beta_thr);
                spk = (v_pre >= thr); s4.z = spk ? 1.0f : 0.0f; vv = spk ? 0.0f : v_pre;
                v_pre = fmaf(alpha, vv, one_m_alpha * in4.w);
                z4.w = fmaf(BETA, v_pre, -beta_thr);
                spk = (v_pre >= thr); s4.w = spk ? 1.0f : 0.0f; vv = spk ? 0.0f : v_pre;
                *(float4*)(zt + off) = z4;                        // STS.128
                *(float4*)(st + off) = s4;                        // STS.128
            }
        }
        __syncthreads();   // tiles complete; input stage si consumed

        if (tid == 0) {
            // refill input stage si first (keeps load stream ahead)
            if (k + 2 < NCH) {
                const int tn = (k + 2) * CHUNK;
                const uint32_t dst = sb + IN_OFF + si * IN_STG;
                mbar_expect_tx(sb + BARB(si), tx_bytes);
                tma_load_2d(dst,               tin, tn,      row0, sb + BARB(si));
                tma_load_2d(dst + TILE_STRIDE, tin, tn + 32, row0, sb + BARB(si));
            }
            asm volatile("fence.proxy.async.shared::cta;" ::: "memory");
            const int t0 = k * CHUNK;
            const uint32_t slot = sb + ST_OFF + si * ST_SLOT;
            tma_store_2d(tz,  t0,      row0, slot);
            tma_store_2d(tz,  t0 + 32, row0, slot + TILE_STRIDE);
            tma_store_2d(tsm, t0,      row0, slot + 2 * TILE_STRIDE);
            tma_store_2d(tsm, t0 + 32, row0, slot + 3 * TILE_STRIDE);
            asm volatile("cp.async.bulk.commit_group;" ::: "memory");
            // store slot si is rewritten 2 chunks from now -> pace to depth 1
            asm volatile("cp.async.bulk.wait_group 1;" ::: "memory");
        }
        __syncthreads();
    }

    if (tid == 0)
        asm volatile("cp.async.bulk.wait_group 0;" ::: "memory");
}

// ---------------- host side ----------------

typedef CUresult (*EncodeFn)(CUtensorMap*, CUtensorMapDataType, cuuint32_t, void*,
                             const cuuint64_t*, const cuuint64_t*,
                             const cuuint32_t*, const cuuint32_t*,
                             CUtensorMapInterleave, CUtensorMapSwizzle,
                             CUtensorMapL2promotion, CUtensorMapFloatOOBfill);

static void make_map(EncodeFn enc, CUtensorMap* m, void* base, unsigned H) {
    cuuint64_t dims[2]    = {LL, (cuuint64_t)BB * FF};
    cuuint64_t strides[1] = {LL * sizeof(float)};
    cuuint32_t box[2]     = {32, H};
    cuuint32_t es[2]      = {1, 1};
    enc(m, CU_TENSOR_MAP_DATA_TYPE_FLOAT32, 2, base, dims, strides, box, es,
        CU_TENSOR_MAP_INTERLEAVE_NONE, CU_TENSOR_MAP_SWIZZLE_128B,
        CU_TENSOR_MAP_L2_PROMOTION_L2_128B, CU_TENSOR_MAP_FLOAT_OOB_FILL_NONE);
}

extern "C" void kernel_launch(void* const* d_in, const int* in_sizes, int n_in,
                              void* d_out, int out_size)
{
    float* I             = (float*)d_in[0];
    const float* raw_tau = (const float*)d_in[1];
    const float* thr     = (const float*)d_in[2];
    float* out           = (float*)d_out;

    static EncodeFn enc = nullptr;
    if (!enc) {
        cudaDriverEntryPointQueryResult qr;
        void* fp = nullptr;
        cudaGetDriverEntryPoint("cuTensorMapEncodeTiled", &fp,
                                cudaEnableDefault, &qr);
        enc = (EncodeFn)fp;
        cudaFuncSetAttribute(lif_tma_kernel,
                             cudaFuncAttributeMaxDynamicSharedMemorySize, SMEM_BYTES);
    }
    if (!enc) return;

    float* sbase = out + (size_t)BB * FF * LL;
    CUtensorMap in_a, in_b, z_a, z_b, s_a, s_b;
    make_map(enc, &in_a, I, 111);     make_map(enc, &in_b, I, 110);
    make_map(enc, &z_a,  out, 111);   make_map(enc, &z_b,  out, 110);
    make_map(enc, &s_a,  sbase, 111); make_map(enc, &s_b,  sbase, 110);

    lif_tma_kernel<<<148, NTH, SMEM_BYTES>>>(in_a, in_b, z_a, z_b, s_a, s_b,
                                             raw_tau, thr);
}